// round 6
// baseline (speedup 1.0000x reference)
#include <cuda_runtime.h>
#include <cuda_bf16.h>
#include <cstdint>

#define TN    8192
#define DD    512
#define NPER  4
#define KNN   5
#define NCAND 8

#define KM      128
#define KNT     128
#define JHALF   (TN / 2)
#define NTILES  (JHALF / KNT)        // 32
#define KCH     64                   // bf16 k per chunk (128B rows, SW128)
#define NCH     (DD / KCH)           // 8
#define TILE_B  16384                // 128 rows x 128 B
#define STAGE_B (4 * TILE_B)         // AiH, AiL, AjH, AjL = 64 KB
#define OFF_D   131072               // stage2 aliases first 64 KB of D region
#define DSTRIDE 130
#define OFF_SQS (OFF_D + KM * DSTRIDE * 4)      // 197632
#define SMEM_TOTAL (OFF_SQS + 512)              // 198144

__device__ float          g_sqn[TN];
__device__ int            g_nn[TN * KNN];
__device__ int            g_choice_is32;
__device__ __nv_bfloat16  g_Ahi[TN * DD];
__device__ __nv_bfloat16  g_Alo[TN * DD];
__device__ int            g_cand_i[TN * 2 * NCAND];

// ============================ helpers =======================================
__device__ __forceinline__ uint32_t smem_u32(const void* p) {
    uint32_t a;
    asm("{ .reg .u64 t; cvta.to.shared.u64 t, %1; cvt.u32.u64 %0, t; }"
        : "=r"(a) : "l"(p));
    return a;
}
__device__ __forceinline__ void cp16(uint32_t dst, const void* src) {
    asm volatile("cp.async.cg.shared.global [%0], [%1], 16;"
                 :: "r"(dst), "l"(src) : "memory");
}
__device__ __forceinline__ void cp_commit() {
    asm volatile("cp.async.commit_group;" ::: "memory");
}
__device__ __forceinline__ void cp_wait0() {
    asm volatile("cp.async.wait_group 0;" ::: "memory");
}
__device__ __forceinline__ void cp_wait1() {
    asm volatile("cp.async.wait_group 1;" ::: "memory");
}
__device__ __forceinline__ void ldsm4(uint32_t* r, uint32_t a) {
    asm volatile("ldmatrix.sync.aligned.m8n8.x4.shared.b16 {%0,%1,%2,%3}, [%4];"
                 : "=r"(r[0]), "=r"(r[1]), "=r"(r[2]), "=r"(r[3]) : "r"(a));
}
__device__ __forceinline__ void mma16816(float* c, const uint32_t* a,
                                         uint32_t b0, uint32_t b1) {
    asm volatile("mma.sync.aligned.m16n8k16.row.col.f32.bf16.bf16.f32 "
                 "{%0,%1,%2,%3}, {%4,%5,%6,%7}, {%8,%9}, {%0,%1,%2,%3};"
                 : "+f"(c[0]), "+f"(c[1]), "+f"(c[2]), "+f"(c[3])
                 : "r"(a[0]), "r"(a[1]), "r"(a[2]), "r"(a[3]),
                   "r"(b0), "r"(b1));
}
__device__ __forceinline__ bool kless(float v, int id, float w, int jd) {
    return (v < w) || (v == w && id < jd);
}
template <int NC>
__device__ __forceinline__ void topk_insert(float (&kv)[NC], int (&ki)[NC],
                                            float v, int j) {
    if (kless(v, j, kv[NC - 1], ki[NC - 1])) {
        kv[NC - 1] = v; ki[NC - 1] = j;
#pragma unroll
        for (int p = NC - 1; p > 0; --p) {
            if (kless(kv[p], ki[p], kv[p - 1], ki[p - 1])) {
                float tv = kv[p]; kv[p] = kv[p - 1]; kv[p - 1] = tv;
                int   tj = ki[p]; ki[p] = ki[p - 1]; ki[p - 1] = tj;
            }
        }
    }
}

// ======================= fp32 -> bf16 hi/lo =================================
__global__ void convert_kernel(const float* __restrict__ A) {
    int idx = blockIdx.x * blockDim.x + threadIdx.x;
    float4 v = reinterpret_cast<const float4*>(A)[idx];
    __nv_bfloat16 h0 = __float2bfloat16(v.x), h1 = __float2bfloat16(v.y);
    __nv_bfloat16 h2 = __float2bfloat16(v.z), h3 = __float2bfloat16(v.w);
    __nv_bfloat16 l0 = __float2bfloat16(v.x - __bfloat162float(h0));
    __nv_bfloat16 l1 = __float2bfloat16(v.y - __bfloat162float(h1));
    __nv_bfloat16 l2 = __float2bfloat16(v.z - __bfloat162float(h2));
    __nv_bfloat16 l3 = __float2bfloat16(v.w - __bfloat162float(h3));
    __nv_bfloat162* ph = reinterpret_cast<__nv_bfloat162*>(g_Ahi);
    __nv_bfloat162* pl = reinterpret_cast<__nv_bfloat162*>(g_Alo);
    ph[idx * 2 + 0] = __nv_bfloat162(h0, h1);
    ph[idx * 2 + 1] = __nv_bfloat162(h2, h3);
    pl[idx * 2 + 0] = __nv_bfloat162(l0, l1);
    pl[idx * 2 + 1] = __nv_bfloat162(l2, l3);
}

// ============================ sq norms ======================================
__global__ void sqnorm_kernel(const float* __restrict__ A) {
    if (blockIdx.x == 0 && threadIdx.x == 0) g_choice_is32 = 0;
    int row = blockIdx.x;
    const float4* p = reinterpret_cast<const float4*>(A + (size_t)row * DD);
    float4 v = p[threadIdx.x];
    float s = v.x * v.x + v.y * v.y + v.z * v.z + v.w * v.w;
#pragma unroll
    for (int off = 16; off > 0; off >>= 1) s += __shfl_xor_sync(0xffffffffu, s, off);
    __shared__ float ws[4];
    int lane = threadIdx.x & 31, wid = threadIdx.x >> 5;
    if (lane == 0) ws[wid] = s;
    __syncthreads();
    if (threadIdx.x == 0) g_sqn[row] = ws[0] + ws[1] + ws[2] + ws[3];
}

// ===================== int32-vs-int64 detection =============================
__global__ void detect_kernel(const unsigned int* __restrict__ w) {
    int idx = blockIdx.x * blockDim.x + threadIdx.x;
    if (w[2 * idx + 1] != 0u) atomicOr(&g_choice_is32, 1);
}

// ================== tensor-core (mma.sync) kNN ==============================
// grid = 128 (64 row-blocks x 2 j-halves), 1024 threads (32 warps).
// Warp grid 4x4x2: (wm, wn) 32x32 output tile, kg splits the 4 k16-steps of
// each chunk (kg=0 -> ks 0,1 ; kg=1 -> ks 2,3). Cross-kg partials are summed
// through the D smem region once per j-tile.
__global__ __launch_bounds__(1024, 1) void knn_mma_kernel() {
    extern __shared__ __align__(16) char smc[];
    const uint32_t sb = smem_u32(smc);
    const int tid  = threadIdx.x;
    const int lane = tid & 31;
    const int wid  = tid >> 5;
    const int kg   = wid >> 4;        // 0..1 k-group
    const int wm   = (wid >> 2) & 3;  // 0..3 -> rows wm*32
    const int wn   = wid & 3;         // 0..3 -> cols wn*32
    const int ib   = blockIdx.x >> 1;
    const int half = blockIdx.x & 1;
    const int brow = ib * KM;
    const int jbase = half * JHALF;

    float kv[NCAND]; int ki[NCAND];
#pragma unroll
    for (int s = 0; s < NCAND; ++s) { kv[s] = 3.4e38f; ki[s] = 0x7fffffff; }

    const int lrow = lane & 15;       // ldsm row within 16
    const int lcol = lane >> 4;       // 0/1 -> 16B half of k16
    const int fr = tid >> 3;          // loader: row 0..127
    const int fq = tid & 7;           // loader: 16B quad 0..7
    const uint32_t fofs = (uint32_t)(fr * 128 + ((fq ^ (fr & 7)) * 16));

    // precomputed swizzled k-offsets for this warp's two k16 steps
    uint32_t kof[2];
#pragma unroll
    for (int s = 0; s < 2; ++s) {
        const int q = kg * 4 + s * 2 + lcol;
        kof[s] = (uint32_t)((q ^ (lrow & 7)) * 16);
    }
    // row base offsets (add stage base per chunk)
    const uint32_t aro = (uint32_t)((wm * 32 + lrow) * 128);
    const uint32_t bro = (uint32_t)((wn * 32 + lrow) * 128);

    // stage smem base offsets (stage 2 aliases D region)
    auto stage_off = [](int s) -> uint32_t {
        return (s == 2) ? (uint32_t)OFF_D : (uint32_t)(s * STAGE_B);
    };

    for (int t = 0; t < NTILES; ++t) {
        const int jb = jbase + t * KNT;

        float acc[2][4][4];
#pragma unroll
        for (int a = 0; a < 2; ++a)
#pragma unroll
            for (int b = 0; b < 4; ++b)
#pragma unroll
                for (int c = 0; c < 4; ++c) acc[a][b][c] = 0.0f;

        // prologue: chunks 0 and 1 -> stages 0, 1
#pragma unroll
        for (int pc = 0; pc < 2; ++pc) {
            const uint32_t stg = sb + stage_off(pc);
            const int kt = pc * KCH;
            const size_t gi = (size_t)(brow + fr) * DD + kt + fq * 8;
            const size_t gj = (size_t)(jb   + fr) * DD + kt + fq * 8;
            cp16(stg + 0 * TILE_B + fofs, g_Ahi + gi);
            cp16(stg + 1 * TILE_B + fofs, g_Alo + gi);
            cp16(stg + 2 * TILE_B + fofs, g_Ahi + gj);
            cp16(stg + 3 * TILE_B + fofs, g_Alo + gj);
            cp_commit();
        }

        for (int c = 0; c < NCH; ++c) {
            if (c == NCH - 1) cp_wait0(); else cp_wait1();
            __syncthreads();

            // prefetch chunk c+2 into stage (c+2)%3
            if (c + 2 < NCH) {
                const uint32_t stg = sb + stage_off((c + 2) % 3);
                const int kt = (c + 2) * KCH;
                const size_t gi = (size_t)(brow + fr) * DD + kt + fq * 8;
                const size_t gj = (size_t)(jb   + fr) * DD + kt + fq * 8;
                cp16(stg + 0 * TILE_B + fofs, g_Ahi + gi);
                cp16(stg + 1 * TILE_B + fofs, g_Alo + gi);
                cp16(stg + 2 * TILE_B + fofs, g_Ahi + gj);
                cp16(stg + 3 * TILE_B + fofs, g_Alo + gj);
                cp_commit();
            }

            // ---- MMA on stage c%3: this warp's 2 k16 steps ----
            const uint32_t base = sb + stage_off(c % 3);
#pragma unroll
            for (int s = 0; s < 2; ++s) {
                uint32_t aH[2][4], aL[2][4], bH[2][4], bL[2][4];
#pragma unroll
                for (int mt = 0; mt < 2; ++mt) {
                    const uint32_t ad = base + aro + (uint32_t)(mt * 16 * 128) + kof[s];
                    ldsm4(aH[mt], ad);
                    ldsm4(aL[mt], ad + TILE_B);
                }
#pragma unroll
                for (int np = 0; np < 2; ++np) {
                    const uint32_t ad = base + 2 * TILE_B + bro +
                                        (uint32_t)(np * 16 * 128) + kof[s];
                    ldsm4(bH[np], ad);
                    ldsm4(bL[np], ad + TILE_B);
                }
#pragma unroll
                for (int mt = 0; mt < 2; ++mt)
#pragma unroll
                    for (int np = 0; np < 2; ++np)
#pragma unroll
                        for (int sel = 0; sel < 2; ++sel) {
                            float* a4 = acc[mt][np * 2 + sel];
                            mma16816(a4, aH[mt], bH[np][sel], bH[np][sel + 2]);
                            mma16816(a4, aH[mt], bL[np][sel], bL[np][sel + 2]);
                            mma16816(a4, aL[mt], bH[np][sel], bH[np][sel + 2]);
                        }
            }
        }

        // ---- cross-kg reduction through D, plus sq[j] staging --------------
        float* Dst = (float*)(smc + OFF_D);
        const int m0 = wm * 32 + (lane >> 2);
        const int n0 = wn * 32 + (lane & 3) * 2;

        if (kg == 1) {
#pragma unroll
            for (int mt = 0; mt < 2; ++mt)
#pragma unroll
                for (int nt = 0; nt < 4; ++nt) {
                    *(float2*)(Dst + (m0 + mt * 16    ) * DSTRIDE + n0 + nt * 8) =
                        make_float2(acc[mt][nt][0], acc[mt][nt][1]);
                    *(float2*)(Dst + (m0 + mt * 16 + 8) * DSTRIDE + n0 + nt * 8) =
                        make_float2(acc[mt][nt][2], acc[mt][nt][3]);
                }
        }
        if (tid < 128)
            *(float*)(smc + OFF_SQS + tid * 4) = g_sqn[jb + tid];
        __syncthreads();
        if (kg == 0) {
#pragma unroll
            for (int mt = 0; mt < 2; ++mt)
#pragma unroll
                for (int nt = 0; nt < 4; ++nt) {
                    float* p0 = Dst + (m0 + mt * 16    ) * DSTRIDE + n0 + nt * 8;
                    float* p1 = Dst + (m0 + mt * 16 + 8) * DSTRIDE + n0 + nt * 8;
                    float2 v0 = *(float2*)p0, v1 = *(float2*)p1;
                    v0.x += acc[mt][nt][0]; v0.y += acc[mt][nt][1];
                    v1.x += acc[mt][nt][2]; v1.y += acc[mt][nt][3];
                    *(float2*)p0 = v0;
                    *(float2*)p1 = v1;
                }
        }
        __syncthreads();

        // ---- selection: 8 threads per row, 16 cols each ----
        {
            const int row = tid & 127, oct = tid >> 7;
            const int grow = brow + row;
            const float* Dp  = (const float*)(smc + OFF_D) + row * DSTRIDE + oct * 16;
            const float* sqp = (const float*)(smc + OFF_SQS) + oct * 16;
            const int j0 = jb + oct * 16;
#pragma unroll
            for (int n = 0; n < 16; ++n) {
                int j = j0 + n;
                float val = sqp[n] - 2.0f * Dp[n];
                if (j != grow) topk_insert<NCAND>(kv, ki, val, j);
            }
        }
        // selection reads of D (stage-2 alias) are fenced from the next
        // tile's stage-2 prefetch by the c=0 __syncthreads of the next loop
    }

    // ---- merge the 8 per-row thread lists, write candidates ---------------
    __syncthreads();
    {
        float* mv = (float*)(smc + OFF_D);
        int*   mi = (int*)(smc + OFF_D) + 1024 * NCAND;
#pragma unroll
        for (int s = 0; s < NCAND; ++s) {
            mv[tid * NCAND + s] = kv[s];
            mi[tid * NCAND + s] = ki[s];
        }
    }
    __syncthreads();
    if (tid < 128) {
        float* mv = (float*)(smc + OFF_D);
        int*   mi = (int*)(smc + OFF_D) + 1024 * NCAND;
#pragma unroll
        for (int o = 1; o < 8; ++o) {
            const int b = (tid + o * 128) * NCAND;
#pragma unroll
            for (int s = 0; s < NCAND; ++s)
                topk_insert<NCAND>(kv, ki, mv[b + s], mi[b + s]);
        }
        const int grow = brow + tid;
        const int base = (grow * 2 + half) * NCAND;
#pragma unroll
        for (int s = 0; s < NCAND; ++s) g_cand_i[base + s] = ki[s];
    }
}

// ========= exact fp32 rescore of 16 candidates -> top-5 =====================
__global__ void rescore_kernel(const float* __restrict__ A) {
    const int row = blockIdx.x;
    const int w = threadIdx.x >> 5, lane = threadIdx.x & 31;  // 16 warps
    __shared__ float sv[16];
    __shared__ int   si[16];
    const int j = g_cand_i[row * 16 + w];
    const float* ai = A + (size_t)row * DD;
    const float* aj = A + (size_t)j * DD;
    float dot = 0.0f;
#pragma unroll
    for (int k = 0; k < 16; ++k) dot += ai[lane + k * 32] * aj[lane + k * 32];
#pragma unroll
    for (int off = 16; off > 0; off >>= 1) dot += __shfl_xor_sync(0xffffffffu, dot, off);
    if (lane == 0) { sv[w] = g_sqn[j] - 2.0f * dot; si[w] = j; }
    __syncthreads();
    if (threadIdx.x == 0) {
        float bv[KNN]; int bi[KNN];
#pragma unroll
        for (int s = 0; s < KNN; ++s) { bv[s] = 3.4e38f; bi[s] = 0x7fffffff; }
        for (int e = 0; e < 16; ++e) {
            float v = sv[e]; int id = si[e];
            if (kless(v, id, bv[KNN - 1], bi[KNN - 1])) {
                bv[KNN - 1] = v; bi[KNN - 1] = id;
#pragma unroll
                for (int p = KNN - 1; p > 0; --p) {
                    if (kless(bv[p], bi[p], bv[p - 1], bi[p - 1])) {
                        float fv = bv[p]; bv[p] = bv[p - 1]; bv[p - 1] = fv;
                        int   iv = bi[p]; bi[p] = bi[p - 1]; bi[p - 1] = iv;
                    }
                }
            }
        }
#pragma unroll
        for (int s = 0; s < KNN; ++s) g_nn[row * KNN + s] = bi[s];
    }
}

// ===================== SMOTE interpolation ==================================
__global__ void populate_kernel(const float* __restrict__ A,
                                const float* __restrict__ gaps,
                                const unsigned int* __restrict__ cw,
                                float* __restrict__ out) {
    int o = blockIdx.x;
    int i = o >> 2;
    float g = gaps[o];
    int widx = g_choice_is32 ? o : (o << 1);
    int c  = (int)cw[widx];
    int nb = g_nn[i * KNN + c];
    const float4* ai = reinterpret_cast<const float4*>(A + (size_t)i  * DD);
    const float4* an = reinterpret_cast<const float4*>(A + (size_t)nb * DD);
    float4* op = reinterpret_cast<float4*>(out) + (size_t)o * (DD / 4);
    int t = threadIdx.x;
    float4 a = ai[t], b = an[t];
    float4 r;
    r.x = a.x + g * (b.x - a.x);
    r.y = a.y + g * (b.y - a.y);
    r.z = a.z + g * (b.z - a.z);
    r.w = a.w + g * (b.w - a.w);
    op[t] = r;
}

// ============================================================================
extern "C" void kernel_launch(void* const* d_in, const int* in_sizes, int n_in,
                              void* d_out, int out_size) {
    const float* A         = (const float*)d_in[0];
    const float* gaps      = (const float*)d_in[1];
    const unsigned int* cw = (const unsigned int*)d_in[2];
    float* out             = (float*)d_out;

    cudaFuncSetAttribute(knn_mma_kernel,
                         cudaFuncAttributeMaxDynamicSharedMemorySize, SMEM_TOTAL);

    convert_kernel<<<TN * DD / 4 / 256, 256>>>(A);
    sqnorm_kernel<<<TN, 128>>>(A);
    detect_kernel<<<64, 256>>>(cw);
    knn_mma_kernel<<<128, 1024, SMEM_TOTAL>>>();
    rescore_kernel<<<TN, 512>>>(A);
    populate_kernel<<<TN * NPER, 128>>>(A, gaps, cw, out);
}

// round 7
// speedup vs baseline: 1.1758x; 1.1758x over previous
#include <cuda_runtime.h>
#include <cuda_bf16.h>
#include <cstdint>

#define TN    8192
#define DD    512
#define NPER  4
#define KNN   5
#define NCAND 8

#define KM      128
#define KNT     128
#define JHALF   (TN / 2)
#define NTILES  (JHALF / KNT)        // 32
#define KCH     64                   // bf16 k per chunk (128B rows, SW128)
#define NCH     (DD / KCH)           // 8
#define TILE_B  16384                // 128 rows x 128 B
#define STAGE_B (4 * TILE_B)         // AiH, AiL, AjH, AjL = 64 KB
#define OFF_D   131072               // stage2 aliases first 64 KB of D region
#define DSTRIDE 130
#define OFF_SQS   (OFF_D + KM * DSTRIDE * 4)    // 197632
#define OFF_LISTS (OFF_SQS + 512)               // 198144
#define SMEM_TOTAL (OFF_LISTS + 512 * NCAND * 8)  // 230912

__device__ float          g_sqn[TN];
__device__ int            g_nn[TN * KNN];
__device__ int            g_choice_is32;
__device__ __nv_bfloat16  g_Ahi[TN * DD];
__device__ __nv_bfloat16  g_Alo[TN * DD];
__device__ int            g_cand_i[TN * 2 * NCAND];

// ============================ helpers =======================================
__device__ __forceinline__ uint32_t smem_u32(const void* p) {
    uint32_t a;
    asm("{ .reg .u64 t; cvta.to.shared.u64 t, %1; cvt.u32.u64 %0, t; }"
        : "=r"(a) : "l"(p));
    return a;
}
__device__ __forceinline__ void cp16(uint32_t dst, const void* src) {
    asm volatile("cp.async.cg.shared.global [%0], [%1], 16;"
                 :: "r"(dst), "l"(src) : "memory");
}
__device__ __forceinline__ void cp_commit() {
    asm volatile("cp.async.commit_group;" ::: "memory");
}
__device__ __forceinline__ void cp_wait0() {
    asm volatile("cp.async.wait_group 0;" ::: "memory");
}
__device__ __forceinline__ void cp_wait1() {
    asm volatile("cp.async.wait_group 1;" ::: "memory");
}
__device__ __forceinline__ void ldsm4(uint32_t* r, uint32_t a) {
    asm volatile("ldmatrix.sync.aligned.m8n8.x4.shared.b16 {%0,%1,%2,%3}, [%4];"
                 : "=r"(r[0]), "=r"(r[1]), "=r"(r[2]), "=r"(r[3]) : "r"(a));
}
__device__ __forceinline__ void mma16816(float* c, const uint32_t* a,
                                         uint32_t b0, uint32_t b1) {
    asm volatile("mma.sync.aligned.m16n8k16.row.col.f32.bf16.bf16.f32 "
                 "{%0,%1,%2,%3}, {%4,%5,%6,%7}, {%8,%9}, {%0,%1,%2,%3};"
                 : "+f"(c[0]), "+f"(c[1]), "+f"(c[2]), "+f"(c[3])
                 : "r"(a[0]), "r"(a[1]), "r"(a[2]), "r"(a[3]),
                   "r"(b0), "r"(b1));
}
__device__ __forceinline__ bool kless(float v, int id, float w, int jd) {
    return (v < w) || (v == w && id < jd);
}
template <int NC>
__device__ __forceinline__ void topk_insert(float (&kv)[NC], int (&ki)[NC],
                                            float v, int j) {
    if (kless(v, j, kv[NC - 1], ki[NC - 1])) {
        kv[NC - 1] = v; ki[NC - 1] = j;
#pragma unroll
        for (int p = NC - 1; p > 0; --p) {
            if (kless(kv[p], ki[p], kv[p - 1], ki[p - 1])) {
                float tv = kv[p]; kv[p] = kv[p - 1]; kv[p - 1] = tv;
                int   tj = ki[p]; ki[p] = ki[p - 1]; ki[p - 1] = tj;
            }
        }
    }
}
// sorted (ascending) top-NCAND list kept in smem; (tv, tj) = reg threshold
__device__ __forceinline__ void insert_smem(uint32_t Lb, float v, int j,
                                            float& tv, int& tj) {
    int p = NCAND - 1;
    for (; p > 0; --p) {
        float ex, ey;
        asm volatile("ld.shared.v2.f32 {%0,%1}, [%2];"
                     : "=f"(ex), "=f"(ey) : "r"(Lb + (p - 1) * 8));
        if (kless(ex, __float_as_int(ey), v, j)) break;
        asm volatile("st.shared.v2.f32 [%0], {%1,%2};"
                     :: "r"(Lb + p * 8), "f"(ex), "f"(ey) : "memory");
    }
    asm volatile("st.shared.v2.f32 [%0], {%1,%2};"
                 :: "r"(Lb + p * 8), "f"(v), "f"(__int_as_float(j)) : "memory");
    float lx, ly;
    asm volatile("ld.shared.v2.f32 {%0,%1}, [%2];"
                 : "=f"(lx), "=f"(ly) : "r"(Lb + (NCAND - 1) * 8));
    tv = lx; tj = __float_as_int(ly);
}

// ======================= fp32 -> bf16 hi/lo =================================
__global__ void convert_kernel(const float* __restrict__ A) {
    int idx = blockIdx.x * blockDim.x + threadIdx.x;
    float4 v = reinterpret_cast<const float4*>(A)[idx];
    __nv_bfloat16 h0 = __float2bfloat16(v.x), h1 = __float2bfloat16(v.y);
    __nv_bfloat16 h2 = __float2bfloat16(v.z), h3 = __float2bfloat16(v.w);
    __nv_bfloat16 l0 = __float2bfloat16(v.x - __bfloat162float(h0));
    __nv_bfloat16 l1 = __float2bfloat16(v.y - __bfloat162float(h1));
    __nv_bfloat16 l2 = __float2bfloat16(v.z - __bfloat162float(h2));
    __nv_bfloat16 l3 = __float2bfloat16(v.w - __bfloat162float(h3));
    __nv_bfloat162* ph = reinterpret_cast<__nv_bfloat162*>(g_Ahi);
    __nv_bfloat162* pl = reinterpret_cast<__nv_bfloat162*>(g_Alo);
    ph[idx * 2 + 0] = __nv_bfloat162(h0, h1);
    ph[idx * 2 + 1] = __nv_bfloat162(h2, h3);
    pl[idx * 2 + 0] = __nv_bfloat162(l0, l1);
    pl[idx * 2 + 1] = __nv_bfloat162(l2, l3);
}

// ============================ sq norms ======================================
__global__ void sqnorm_kernel(const float* __restrict__ A) {
    if (blockIdx.x == 0 && threadIdx.x == 0) g_choice_is32 = 0;
    int row = blockIdx.x;
    const float4* p = reinterpret_cast<const float4*>(A + (size_t)row * DD);
    float4 v = p[threadIdx.x];
    float s = v.x * v.x + v.y * v.y + v.z * v.z + v.w * v.w;
#pragma unroll
    for (int off = 16; off > 0; off >>= 1) s += __shfl_xor_sync(0xffffffffu, s, off);
    __shared__ float ws[4];
    int lane = threadIdx.x & 31, wid = threadIdx.x >> 5;
    if (lane == 0) ws[wid] = s;
    __syncthreads();
    if (threadIdx.x == 0) g_sqn[row] = ws[0] + ws[1] + ws[2] + ws[3];
}

// ===================== int32-vs-int64 detection =============================
__global__ void detect_kernel(const unsigned int* __restrict__ w) {
    int idx = blockIdx.x * blockDim.x + threadIdx.x;
    if (w[2 * idx + 1] != 0u) atomicOr(&g_choice_is32, 1);
}

// ================== tensor-core (mma.sync) kNN ==============================
// grid = 128 (64 row-blocks x 2 j-halves), 512 threads (16 warps, 4x4 grid),
// warp tile 32x32, fragment double-buffering across the 4 k16 steps/chunk.
__global__ __launch_bounds__(512, 1) void knn_mma_kernel() {
    extern __shared__ __align__(16) char smc[];
    const uint32_t sb = smem_u32(smc);
    const int tid  = threadIdx.x;
    const int lane = tid & 31;
    const int wid  = tid >> 5;
    const int wm   = wid >> 2;      // 0..3 -> rows wm*32
    const int wn   = wid & 3;       // 0..3 -> cols wn*32
    const int ib   = blockIdx.x >> 1;
    const int half = blockIdx.x & 1;
    const int brow = ib * KM;
    const int jbase = half * JHALF;

    const int lrow = lane & 15;
    const int lcol = lane >> 4;
    const int fr = tid >> 2;        // loader: row 0..127
    const int fq0 = (tid & 3) * 2;  // loader: quads q, q+1

    // precomputed swizzled k offsets for the 4 k16 steps
    uint32_t kof[4];
#pragma unroll
    for (int ks = 0; ks < 4; ++ks)
        kof[ks] = (uint32_t)(((ks * 2 + lcol) ^ (lrow & 7)) * 16);
    const uint32_t aro = (uint32_t)((wm * 32 + lrow) * 128);
    const uint32_t bro = (uint32_t)((wn * 32 + lrow) * 128);

    // per-thread smem candidate list + register threshold
    const uint32_t Lb = sb + OFF_LISTS + tid * (NCAND * 8);
#pragma unroll
    for (int s = 0; s < NCAND; ++s)
        asm volatile("st.shared.v2.f32 [%0], {%1,%2};"
                     :: "r"(Lb + s * 8), "f"(3.4e38f),
                        "f"(__int_as_float(0x7fffffff)) : "memory");
    float tv = 3.4e38f; int tj = 0x7fffffff;

    auto stage_off = [](int s) -> uint32_t {
        return (s == 2) ? (uint32_t)OFF_D : (uint32_t)(s * STAGE_B);
    };

    uint32_t aH0[2][4], aL0[2][4], bH0[2][4], bL0[2][4];
    uint32_t aH1[2][4], aL1[2][4], bH1[2][4], bL1[2][4];

#define LOAD_FRAGS(B, KS) do {                                              \
    const uint32_t kf = kof[KS];                                            \
    const uint32_t ad = base + aro + kf;                                    \
    ldsm4(aH##B[0], ad);        ldsm4(aL##B[0], ad + TILE_B);               \
    ldsm4(aH##B[1], ad + 2048); ldsm4(aL##B[1], ad + 2048 + TILE_B);        \
    const uint32_t bd = base + 2 * TILE_B + bro + kf;                       \
    ldsm4(bH##B[0], bd);        ldsm4(bL##B[0], bd + TILE_B);               \
    ldsm4(bH##B[1], bd + 2048); ldsm4(bL##B[1], bd + 2048 + TILE_B);        \
} while (0)

#define MMA_STEP(B) do {                                                    \
    _Pragma("unroll")                                                       \
    for (int mt = 0; mt < 2; ++mt)                                          \
        _Pragma("unroll")                                                   \
        for (int np = 0; np < 2; ++np)                                      \
            _Pragma("unroll")                                               \
            for (int sel = 0; sel < 2; ++sel) {                             \
                float* a4 = acc[mt][np * 2 + sel];                          \
                mma16816(a4, aH##B[mt], bH##B[np][sel], bH##B[np][sel + 2]);\
                mma16816(a4, aH##B[mt], bL##B[np][sel], bL##B[np][sel + 2]);\
                mma16816(a4, aL##B[mt], bH##B[np][sel], bH##B[np][sel + 2]);\
            }                                                               \
} while (0)

    for (int t = 0; t < NTILES; ++t) {
        const int jb = jbase + t * KNT;

        float acc[2][4][4];
#pragma unroll
        for (int a = 0; a < 2; ++a)
#pragma unroll
            for (int b = 0; b < 4; ++b)
#pragma unroll
                for (int c = 0; c < 4; ++c) acc[a][b][c] = 0.0f;

        // prologue: chunks 0 and 1 -> stages 0, 1
#pragma unroll
        for (int pc = 0; pc < 2; ++pc) {
            const uint32_t stg = sb + stage_off(pc);
            const int kt = pc * KCH;
#pragma unroll
            for (int i = 0; i < 2; ++i) {
                const int q = fq0 + i;
                const uint32_t dofs = (uint32_t)(fr * 128 + ((q ^ (fr & 7)) * 16));
                const size_t gi = (size_t)(brow + fr) * DD + kt + q * 8;
                const size_t gj = (size_t)(jb   + fr) * DD + kt + q * 8;
                cp16(stg + 0 * TILE_B + dofs, g_Ahi + gi);
                cp16(stg + 1 * TILE_B + dofs, g_Alo + gi);
                cp16(stg + 2 * TILE_B + dofs, g_Ahi + gj);
                cp16(stg + 3 * TILE_B + dofs, g_Alo + gj);
            }
            cp_commit();
        }

        for (int c = 0; c < NCH; ++c) {
            if (c == NCH - 1) cp_wait0(); else cp_wait1();
            __syncthreads();

            // prefetch chunk c+2 into stage (c+2)%3
            if (c + 2 < NCH) {
                const uint32_t stg = sb + stage_off((c + 2) % 3);
                const int kt = (c + 2) * KCH;
#pragma unroll
                for (int i = 0; i < 2; ++i) {
                    const int q = fq0 + i;
                    const uint32_t dofs = (uint32_t)(fr * 128 + ((q ^ (fr & 7)) * 16));
                    const size_t gi = (size_t)(brow + fr) * DD + kt + q * 8;
                    const size_t gj = (size_t)(jb   + fr) * DD + kt + q * 8;
                    cp16(stg + 0 * TILE_B + dofs, g_Ahi + gi);
                    cp16(stg + 1 * TILE_B + dofs, g_Alo + gi);
                    cp16(stg + 2 * TILE_B + dofs, g_Ahi + gj);
                    cp16(stg + 3 * TILE_B + dofs, g_Alo + gj);
                }
                cp_commit();
            }

            // ---- MMA with double-buffered fragments ----
            const uint32_t base = sb + stage_off(c % 3);
            LOAD_FRAGS(0, 0);
            LOAD_FRAGS(1, 1);
            MMA_STEP(0);
            LOAD_FRAGS(0, 2);
            MMA_STEP(1);
            LOAD_FRAGS(1, 3);
            MMA_STEP(0);
            MMA_STEP(1);
        }

        // ---- stage d2 dot values + sq[j] to smem ----
        if (tid < 128)
            *(float*)(smc + OFF_SQS + tid * 4) = g_sqn[jb + tid];
        {
            float* Dst = (float*)(smc + OFF_D);
            const int m0 = wm * 32 + (lane >> 2);
            const int n0 = wn * 32 + (lane & 3) * 2;
#pragma unroll
            for (int mt = 0; mt < 2; ++mt)
#pragma unroll
                for (int nt = 0; nt < 4; ++nt) {
                    *(float2*)(Dst + (m0 + mt * 16    ) * DSTRIDE + n0 + nt * 8) =
                        make_float2(acc[mt][nt][0], acc[mt][nt][1]);
                    *(float2*)(Dst + (m0 + mt * 16 + 8) * DSTRIDE + n0 + nt * 8) =
                        make_float2(acc[mt][nt][2], acc[mt][nt][3]);
                }
        }
        __syncthreads();

        // ---- selection: 4 threads per row, 32 cols each, smem lists ----
        {
            const int row = tid & 127, qtr = tid >> 7;
            const int grow = brow + row;
            const float* Dp  = (const float*)(smc + OFF_D) + row * DSTRIDE + qtr * 32;
            const float* sqp = (const float*)(smc + OFF_SQS) + qtr * 32;
            const int j0 = jb + qtr * 32;
#pragma unroll 8
            for (int n = 0; n < 32; ++n) {
                int j = j0 + n;
                float val = sqp[n] - 2.0f * Dp[n];
                if (j != grow && kless(val, j, tv, tj))
                    insert_smem(Lb, val, j, tv, tj);
            }
        }
        // selection reads of D (stage-2 alias) are fenced from the next
        // tile's stage-2 prefetch by the c=0 __syncthreads of the next loop
    }

    // ---- merge the 4 per-row smem lists, write candidates ------------------
    __syncthreads();
    if (tid < 128) {
        float kv[NCAND]; int ki[NCAND];
#pragma unroll
        for (int s = 0; s < NCAND; ++s) { kv[s] = 3.4e38f; ki[s] = 0x7fffffff; }
#pragma unroll
        for (int o = 0; o < 4; ++o) {
            const uint32_t Lo = sb + OFF_LISTS + (tid + o * 128) * (NCAND * 8);
#pragma unroll
            for (int s = 0; s < NCAND; ++s) {
                float ex, ey;
                asm volatile("ld.shared.v2.f32 {%0,%1}, [%2];"
                             : "=f"(ex), "=f"(ey) : "r"(Lo + s * 8));
                topk_insert<NCAND>(kv, ki, ex, __float_as_int(ey));
            }
        }
        const int grow = brow + tid;
        const int base = (grow * 2 + half) * NCAND;
#pragma unroll
        for (int s = 0; s < NCAND; ++s) g_cand_i[base + s] = ki[s];
    }
#undef LOAD_FRAGS
#undef MMA_STEP
}

// ========= exact fp32 rescore of 16 candidates -> top-5 =====================
__global__ void rescore_kernel(const float* __restrict__ A) {
    const int row = blockIdx.x;
    const int w = threadIdx.x >> 5, lane = threadIdx.x & 31;  // 16 warps
    __shared__ float sv[16];
    __shared__ int   si[16];
    const int j = g_cand_i[row * 16 + w];
    const float* ai = A + (size_t)row * DD;
    const float* aj = A + (size_t)j * DD;
    float dot = 0.0f;
#pragma unroll
    for (int k = 0; k < 16; ++k) dot += ai[lane + k * 32] * aj[lane + k * 32];
#pragma unroll
    for (int off = 16; off > 0; off >>= 1) dot += __shfl_xor_sync(0xffffffffu, dot, off);
    if (lane == 0) { sv[w] = g_sqn[j] - 2.0f * dot; si[w] = j; }
    __syncthreads();
    if (threadIdx.x == 0) {
        float bv[KNN]; int bi[KNN];
#pragma unroll
        for (int s = 0; s < KNN; ++s) { bv[s] = 3.4e38f; bi[s] = 0x7fffffff; }
        for (int e = 0; e < 16; ++e) {
            float v = sv[e]; int id = si[e];
            if (kless(v, id, bv[KNN - 1], bi[KNN - 1])) {
                bv[KNN - 1] = v; bi[KNN - 1] = id;
#pragma unroll
                for (int p = KNN - 1; p > 0; --p) {
                    if (kless(bv[p], bi[p], bv[p - 1], bi[p - 1])) {
                        float fv = bv[p]; bv[p] = bv[p - 1]; bv[p - 1] = fv;
                        int   iv = bi[p]; bi[p] = bi[p - 1]; bi[p - 1] = iv;
                    }
                }
            }
        }
#pragma unroll
        for (int s = 0; s < KNN; ++s) g_nn[row * KNN + s] = bi[s];
    }
}

// ===================== SMOTE interpolation ==================================
__global__ void populate_kernel(const float* __restrict__ A,
                                const float* __restrict__ gaps,
                                const unsigned int* __restrict__ cw,
                                float* __restrict__ out) {
    int o = blockIdx.x;
    int i = o >> 2;
    float g = gaps[o];
    int widx = g_choice_is32 ? o : (o << 1);
    int c  = (int)cw[widx];
    int nb = g_nn[i * KNN + c];
    const float4* ai = reinterpret_cast<const float4*>(A + (size_t)i  * DD);
    const float4* an = reinterpret_cast<const float4*>(A + (size_t)nb * DD);
    float4* op = reinterpret_cast<float4*>(out) + (size_t)o * (DD / 4);
    int t = threadIdx.x;
    float4 a = ai[t], b = an[t];
    float4 r;
    r.x = a.x + g * (b.x - a.x);
    r.y = a.y + g * (b.y - a.y);
    r.z = a.z + g * (b.z - a.z);
    r.w = a.w + g * (b.w - a.w);
    op[t] = r;
}

// ============================================================================
extern "C" void kernel_launch(void* const* d_in, const int* in_sizes, int n_in,
                              void* d_out, int out_size) {
    const float* A         = (const float*)d_in[0];
    const float* gaps      = (const float*)d_in[1];
    const unsigned int* cw = (const unsigned int*)d_in[2];
    float* out             = (float*)d_out;

    cudaFuncSetAttribute(knn_mma_kernel,
                         cudaFuncAttributeMaxDynamicSharedMemorySize, SMEM_TOTAL);

    convert_kernel<<<TN * DD / 4 / 256, 256>>>(A);
    sqnorm_kernel<<<TN, 128>>>(A);
    detect_kernel<<<64, 256>>>(cw);
    knn_mma_kernel<<<128, 512, SMEM_TOTAL>>>();
    rescore_kernel<<<TN, 512>>>(A);
    populate_kernel<<<TN * NPER, 128>>>(A, gaps, cw, out);
}